// round 2
// baseline (speedup 1.0000x reference)
#include <cuda_runtime.h>
#include <cstdint>
#include <math.h>

#define SEQ   4096
#define EMB   256
#define H     256
#define G4    1024   // 4*H
#define NTAGS 32

// ---------------- scratch (device globals: no allocation allowed) ----------
__device__ float g_gx[2][SEQ][G4];     // input projections per direction
__device__ float g_hs[SEQ][2 * H];     // concatenated BiLSTM hidden states
__device__ float g_em[SEQ][NTAGS];     // emissions

__device__ __forceinline__ unsigned smem_u32(const void* p) {
    return (unsigned)__cvta_generic_to_shared(p);
}

#define CLUSTER_SYNC_ASM() do { \
    asm volatile("barrier.cluster.arrive.aligned;" ::: "memory"); \
    asm volatile("barrier.cluster.wait.aligned;"   ::: "memory"); \
} while (0)

// ============================================================================
// Kernel A: gx[d][t][r] = emb_d[t] . w_ih_d[r] + b_ih[r] + b_hh[r]
// emb_d[t] = embed[x[t]] (fwd) or embed[x[SEQ-1-t]] (bwd)
// grid (SEQ/64, G4/64, 2), block 256.  Tiles 64x64, BK=32.
// ============================================================================
__global__ void gx_kernel(const float* __restrict__ embed,
                          const float* __restrict__ w_ih_f,
                          const float* __restrict__ b_ih_f,
                          const float* __restrict__ b_hh_f,
                          const float* __restrict__ w_ih_b,
                          const float* __restrict__ b_ih_b,
                          const float* __restrict__ b_hh_b,
                          const int*   __restrict__ x)
{
    const int dir = blockIdx.z;
    const float* w_ih = dir ? w_ih_b : w_ih_f;
    const float* b_ih = dir ? b_ih_b : b_ih_f;
    const float* b_hh = dir ? b_hh_b : b_hh_f;

    __shared__ float As[64][33];
    __shared__ float Bs[64][33];
    __shared__ int   toks[64];

    const int tid = threadIdx.x;
    const int t0 = blockIdx.x * 64;
    const int r0 = blockIdx.y * 64;

    if (tid < 64) {
        int t = t0 + tid;
        int p = dir ? (SEQ - 1 - t) : t;
        toks[tid] = x[p];
    }
    __syncthreads();

    const int tx = tid & 15, ty = tid >> 4;
    float c[4][4] = {};

    for (int k0 = 0; k0 < EMB; k0 += 32) {
        for (int i = tid; i < 64 * 32; i += 256) {
            int row = i >> 5, k = i & 31;
            As[row][k] = embed[(size_t)toks[row] * EMB + k0 + k];
        }
        for (int i = tid; i < 64 * 32; i += 256) {
            int row = i >> 5, k = i & 31;
            Bs[row][k] = w_ih[(size_t)(r0 + row) * EMB + k0 + k];
        }
        __syncthreads();
        #pragma unroll
        for (int kk = 0; kk < 32; kk++) {
            float a[4], b[4];
            #pragma unroll
            for (int u = 0; u < 4; u++) a[u] = As[ty * 4 + u][kk];
            #pragma unroll
            for (int v = 0; v < 4; v++) b[v] = Bs[tx * 4 + v][kk];
            #pragma unroll
            for (int u = 0; u < 4; u++)
                #pragma unroll
                for (int v = 0; v < 4; v++)
                    c[u][v] += a[u] * b[v];
        }
        __syncthreads();
    }

    #pragma unroll
    for (int u = 0; u < 4; u++) {
        int t = t0 + ty * 4 + u;
        #pragma unroll
        for (int v = 0; v < 4; v++) {
            int r = r0 + tx * 4 + v;
            g_gx[dir][t][r] = c[u][v] + b_ih[r] + b_hh[r];
        }
    }
}

// ============================================================================
// Kernel B: sequential BiLSTM recurrence.
// grid 16 CTAs = 2 clusters of 8 (cluster 0 = fwd, cluster 1 = bwd).
// Each CTA owns 32 hidden units (128 gate rows); W_hh slice lives in REGISTERS
// (64 floats / thread, 512 threads).  h (256 floats) broadcast to all 8 CTAs
// each step via st.shared::cluster; double-buffered so one cluster.sync/step.
// ============================================================================
__global__ void __cluster_dims__(8, 1, 1) __launch_bounds__(512, 1)
lstm_kernel(const float* __restrict__ w_hh_f, const float* __restrict__ w_hh_b)
{
    __shared__ __align__(16) float sh_h[2][256];
    __shared__ float red[512];

    const int tid = threadIdx.x;
    const int dir = blockIdx.x >> 3;
    unsigned rank;
    asm("mov.u32 %0, %%cluster_ctarank;" : "=r"(rank));
    const int j0 = (int)rank * 32;

    const float* __restrict__ w_hh = dir ? w_hh_b : w_hh_f;

    // thread -> (gate row, K-slice).  Warp lanes share the slice s, so the
    // sh_h reads below are pure broadcasts (conflict-free).
    const int g    = ((tid >> 7) << 5) | (tid & 31);  // 0..127 local gate id
    const int s    = (tid >> 5) & 3;                  // 0..3  K slice
    const int gate = g >> 5;                          // i,f,g,o
    const int j    = g & 31;                          // hidden index within CTA
    const int row  = gate * H + j0 + j;               // global gate row

    float w[64];
    #pragma unroll
    for (int q = 0; q < 64; q++)
        w[q] = w_hh[(size_t)row * H + s * 64 + q];

    if (tid < 256) { sh_h[0][tid] = 0.f; sh_h[1][tid] = 0.f; }

    // remote addresses for the per-step h broadcast (threads j<32 only)
    unsigned raddr[2][8];
    if (tid < 32) {
        #pragma unroll
        for (int b = 0; b < 2; b++) {
            unsigned la = smem_u32(&sh_h[b][j0 + tid]);
            #pragma unroll
            for (int cc = 0; cc < 8; cc++) {
                unsigned ra;
                asm("mapa.shared::cluster.u32 %0, %1, %2;"
                    : "=r"(ra) : "r"(la), "r"(cc));
                raddr[b][cc] = ra;
            }
        }
    }

    float cstate = 0.f;
    const float* __restrict__ gx_base = &g_gx[dir][0][0];

    CLUSTER_SYNC_ASM();   // zeros visible before anyone's step-0 remote writes

    for (int step = 0; step < SEQ; step++) {
        const int rb = step & 1;   // buffer holding h_{t-1}
        const int wb = rb ^ 1;     // buffer receiving h_t

        // prefetch gx[step] early; consumed ~500cyc later in phase 2
        float gxv0 = 0.f, gxv1 = 0.f, gxv2 = 0.f, gxv3 = 0.f;
        if (tid < 32) {
            const float* p = gx_base + (size_t)step * G4 + j0 + tid;
            gxv0 = __ldg(p + 0 * H);
            gxv1 = __ldg(p + 1 * H);
            gxv2 = __ldg(p + 2 * H);
            gxv3 = __ldg(p + 3 * H);
        }

        // phase 1: partial dot over this thread's 64-wide K slice
        const float4* hv = (const float4*)&sh_h[rb][s * 64];
        float a0 = 0.f, a1 = 0.f, a2 = 0.f, a3 = 0.f;
        #pragma unroll
        for (int q = 0; q < 16; q++) {
            float4 h4 = hv[q];
            a0 += w[4 * q + 0] * h4.x;
            a1 += w[4 * q + 1] * h4.y;
            a2 += w[4 * q + 2] * h4.z;
            a3 += w[4 * q + 3] * h4.w;
        }
        red[s * 128 + g] = (a0 + a1) + (a2 + a3);
        __syncthreads();

        // phase 2: 32 owner threads finish gates, cell update, broadcast h
        if (tid < 32) {
            float gi = gxv0, gf = gxv1, gg = gxv2, go = gxv3;
            #pragma unroll
            for (int sl = 0; sl < 4; sl++) {
                gi += red[sl * 128 + 0 * 32 + tid];
                gf += red[sl * 128 + 1 * 32 + tid];
                gg += red[sl * 128 + 2 * 32 + tid];
                go += red[sl * 128 + 3 * 32 + tid];
            }
            float iv = 1.f / (1.f + __expf(-gi));
            float fv = 1.f / (1.f + __expf(-gf));
            float gv = tanhf(gg);
            float ov = 1.f / (1.f + __expf(-go));
            cstate = fv * cstate + iv * gv;
            float h = ov * tanhf(cstate);
            #pragma unroll
            for (int cc = 0; cc < 8; cc++)
                asm volatile("st.shared::cluster.f32 [%0], %1;"
                             :: "r"(raddr[wb][cc]), "f"(h));
            int pos = dir ? (SEQ - 1 - step) : step;
            g_hs[pos][dir * H + j0 + tid] = h;
        }
        CLUSTER_SYNC_ASM();  // h_t visible everywhere; also orders red[] reuse
    }
}

// ============================================================================
// Kernel C: emissions em[t][k] = hs[t] . w_lin[k] + b_lin[k]
// grid SEQ blocks, 512 threads (32 tags x 16 K-slices).
// ============================================================================
__global__ void emis_kernel(const float* __restrict__ w_lin,
                            const float* __restrict__ b_lin)
{
    __shared__ float hsm[512];
    __shared__ float redc[512];
    const int t = blockIdx.x, tid = threadIdx.x;
    hsm[tid] = g_hs[t][tid];
    __syncthreads();

    const int k = tid & 31, sl = tid >> 5;
    float p = 0.f;
    #pragma unroll
    for (int m = 0; m < 32; m++)
        p += hsm[sl * 32 + m] * __ldg(&w_lin[k * 512 + sl * 32 + m]);
    redc[sl * 32 + k] = p;
    __syncthreads();

    if (tid < 32) {
        float sum = b_lin[tid];
        #pragma unroll
        for (int s2 = 0; s2 < 16; s2++) sum += redc[s2 * 32 + tid];
        g_em[t][tid] = sum;
    }
}

// ============================================================================
// Kernel D: CRF NLL.  1 block, 1024 threads (warp j computes alpha[j]).
// trans column in registers; shift by alpha[0] (tag-spread bounded) so no
// max-reduction needed in the hot loop; double-buffered alpha, 1 bar/step.
// ============================================================================
__global__ void __launch_bounds__(1024, 1)
crf_kernel(const float* __restrict__ trans,
           const float* __restrict__ start_trans,
           const float* __restrict__ end_trans,
           const int*   __restrict__ y,
           float* __restrict__ out)
{
    __shared__ float alpha[2][NTAGS];
    __shared__ float s_num;
    __shared__ float s_red[32];

    const int tid = threadIdx.x;
    const int lane = tid & 31, warp = tid >> 5;

    // ---- gold path score (numerator) ----
    float part = 0.f;
    for (int t = tid; t < SEQ; t += 1024) {
        int yt = y[t];
        part += g_em[t][yt];
        if (t > 0) part += trans[y[t - 1] * NTAGS + yt];
    }
    #pragma unroll
    for (int o = 16; o; o >>= 1) part += __shfl_xor_sync(~0u, part, o);
    if (lane == 0) s_red[warp] = part;
    __syncthreads();
    if (tid == 0) {
        float num = start_trans[y[0]] + end_trans[y[SEQ - 1]];
        #pragma unroll
        for (int wv = 0; wv < 32; wv++) num += s_red[wv];
        s_num = num;
    }
    if (tid < NTAGS) alpha[0][tid] = start_trans[tid] + g_em[0][tid];
    __syncthreads();

    // ---- forward algorithm ----
    const float treg = trans[lane * NTAGS + warp];  // trans[i=lane][j=warp]
    float emv = g_em[1][warp];                       // prefetch step 1
    for (int t = 1; t < SEQ; t++) {
        const int rp = (t - 1) & 1, wp = t & 1;
        float a   = alpha[rp][lane];
        float ref = alpha[rp][0];
        float e = __expf(a + treg - ref);
        #pragma unroll
        for (int o = 16; o; o >>= 1) e += __shfl_xor_sync(~0u, e, o);
        float em_cur = emv;
        if (t + 1 < SEQ) emv = g_em[t + 1][warp];
        if (lane == 0) alpha[wp][warp] = ref + __logf(e) + em_cur;
        __syncthreads();
    }

    if (warp == 0) {
        float v = alpha[(SEQ - 1) & 1][lane] + end_trans[lane];
        float m = v;
        #pragma unroll
        for (int o = 16; o; o >>= 1) m = fmaxf(m, __shfl_xor_sync(~0u, m, o));
        float e = __expf(v - m);
        #pragma unroll
        for (int o = 16; o; o >>= 1) e += __shfl_xor_sync(~0u, e, o);
        if (lane == 0) out[0] = (m + __logf(e)) - s_num;
    }
}

// ============================================================================
extern "C" void kernel_launch(void* const* d_in, const int* in_sizes, int n_in,
                              void* d_out, int out_size)
{
    const float* embed       = (const float*)d_in[0];
    const float* w_ih_f      = (const float*)d_in[1];
    const float* w_hh_f      = (const float*)d_in[2];
    const float* b_ih_f      = (const float*)d_in[3];
    const float* b_hh_f      = (const float*)d_in[4];
    const float* w_ih_b      = (const float*)d_in[5];
    const float* w_hh_b      = (const float*)d_in[6];
    const float* b_ih_b      = (const float*)d_in[7];
    const float* b_hh_b      = (const float*)d_in[8];
    const float* w_lin       = (const float*)d_in[9];
    const float* b_lin       = (const float*)d_in[10];
    const float* trans       = (const float*)d_in[11];
    const float* start_trans = (const float*)d_in[12];
    const float* end_trans   = (const float*)d_in[13];
    const int*   x           = (const int*)d_in[14];
    const int*   y           = (const int*)d_in[15];

    dim3 gA(SEQ / 64, G4 / 64, 2);
    gx_kernel<<<gA, 256>>>(embed, w_ih_f, b_ih_f, b_hh_f,
                           w_ih_b, b_ih_b, b_hh_b, x);
    lstm_kernel<<<16, 512>>>(w_hh_f, w_hh_b);
    emis_kernel<<<SEQ, 512>>>(w_lin, b_lin);
    crf_kernel<<<1, 1024>>>(trans, start_trans, end_trans, y, (float*)d_out);
}